// round 9
// baseline (speedup 1.0000x reference)
#include <cuda_runtime.h>
#include <math.h>

#define XS 540
#define YS 540
#define BATCH 4
#define NBOX 64
#define TILE 32
#define TXN 17
#define TYN 17
#define NBLOCKS (TXN*TYN*BATCH)
#define FIXSCALE 67108864.0   // 2^26

__device__ unsigned long long g_acc[BATCH][2];
__device__ unsigned int g_done;

struct BoxC { float cx, cy, c, s, hw, hl, hv; };

__global__ void __launch_bounds__(256)
hm_loss_fused_kernel(const float* __restrict__ logits,
                     const float* __restrict__ boxes,
                     const float* __restrict__ hm,
                     float* __restrict__ out)
{
    __shared__ BoxC bc[NBOX];
    __shared__ unsigned int sm_mask[2];
    __shared__ float ws[8];
    __shared__ int   wc[8];

    const int b    = blockIdx.z;
    const int tid  = threadIdx.x;
    const int lane = tid & 31;
    const int wrp  = tid >> 5;

    // ---- box loads FIRST (they feed the barrier everyone waits on) ----
    float p0, p1, p3, p4, p5, p6;
    if (tid < NBOX) {
        const float* p = boxes + (b * NBOX + tid) * 7;
        p0 = p[0]; p1 = p[1]; p3 = p[3]; p4 = p[4]; p5 = p[5]; p6 = p[6];
    }

    // ---- pixel prefetch: thread = 4 contiguous x px in one row ----
    const int x4 = blockIdx.x * TILE + (lane & 7) * 4;
    const int y  = blockIdx.y * TILE + (tid >> 3);
    const bool ok = (x4 + 3 < XS) && (y < YS);

    float4 xl4 = make_float4(0.f, 0.f, 0.f, 0.f);
    float4 hh4 = make_float4(0.f, 0.f, 0.f, 0.f);
    if (ok) {
        const int idx = (b * YS + y) * XS + x4;
        xl4 = *reinterpret_cast<const float4*>(logits + idx);
        hh4 = *reinterpret_cast<const float4*>(hm + idx);
    }

    // ---- box transform + cull + ballot ----
    if (tid < NBOX) {
        BoxC v;
        v.cx = (p0 + 54.0f) * 5.0f;
        v.cy = (p1 + 54.0f) * 5.0f;
        v.hw = p3 * 2.5f;
        v.hl = p4 * 2.5f;
        float sn, cn;
        __sincosf(p6, &sn, &cn);
        v.c  = cn;           // cos(-theta)
        v.s  = -sn;          // sin(-theta)
        v.hv = p5 * 0.2f;
        bc[tid] = v;

        const float ex = fabsf(v.c) * v.hw + fabsf(v.s) * v.hl;
        const float ey = fabsf(v.s) * v.hw + fabsf(v.c) * v.hl;
        const float tx0 = (float)(blockIdx.x * TILE);
        const float ty0 = (float)(blockIdx.y * TILE);
        const bool hit = (v.cx - ex <= tx0 + (float)(TILE - 1)) && (v.cx + ex >= tx0) &&
                         (v.cy - ey <= ty0 + (float)(TILE - 1)) && (v.cy + ey >= ty0);
        const unsigned int m = __ballot_sync(0xffffffffu, hit);
        if (lane == 0) sm_mask[wrp] = m;
    }
    __syncthreads();

    const unsigned int m0 = sm_mask[0];
    const unsigned int m1 = sm_mask[1];

    // ---- raster: forward order, overwrite => last box wins (no guard, no break) ----
    float gt[4] = {0.f, 0.f, 0.f, 0.f};
    {
        const float fx0 = (float)x4;
        const float fy  = (float)y;
        #pragma unroll
        for (int half = 0; half < 2; half++) {
            unsigned int mm = half ? m1 : m0;
            const int base = half ? 32 : 0;
            while (mm) {
                const int i = __ffs(mm) - 1;       // lowest set bit -> ascending order
                mm &= mm - 1u;
                const BoxC v = bc[base + i];
                const float dx = fx0 - v.cx;
                const float dy = fy - v.cy;
                float lx = dx * v.c - dy * v.s;
                float ly = dx * v.s + dy * v.c;
                #pragma unroll
                for (int j = 0; j < 4; j++) {
                    const bool inside = (fabsf(lx) <= v.hw) && (fabsf(ly) <= v.hl);
                    gt[j] = inside ? v.hv : gt[j];
                    lx += v.c;
                    ly += v.s;
                }
            }
        }
    }

    // ---- loss: branch-free, two accumulators for ILP ----
    float sc0 = 0.0f, sc1 = 0.0f;
    int   cv = 0;
    const float* xvp = &xl4.x;
    const float* hhp = &hh4.x;
    #pragma unroll
    for (int j = 0; j < 4; j++) {
        const float g  = gt[j];
        const bool pos = (g > 0.0f);
        const bool valid = ok && (pos || (hhp[j] > 0.0f));
        const float xl = xvp[j];

        const float weight = pos ? 5.0f : 0.1f;
        const float e  = __expf(-fabsf(xl));
        const float d  = 1.0f + e;
        const float bce = fmaxf(xl, 0.0f) - xl * g + __logf(d);
        const float rd = __fdividef(1.0f, d);
        const float p  = (xl >= 0.0f) ? rd : e * rd;    // sigmoid
        const float u  = fmaf(p, 1.0f - 2.0f * g, g);   // 1 - p_t
        const float aw = 0.75f - 0.5f * g;
        const float contrib = weight * bce * fmaf(u * u, aw, 1.0f);
        if (j & 1) sc1 += valid ? contrib : 0.0f;
        else       sc0 += valid ? contrib : 0.0f;
        cv += valid ? 1 : 0;
    }
    float sc = sc0 + sc1;

    const int cnt = __reduce_add_sync(0xffffffffu, cv);
    #pragma unroll
    for (int st = 16; st > 0; st >>= 1)
        sc += __shfl_xor_sync(0xffffffffu, sc, st);
    if (lane == 0) { ws[wrp] = sc; wc[wrp] = cnt; }
    __syncthreads();

    // ---- final combine in warp 0 (8 lanes) ----
    if (tid < 8) {
        float t1 = ws[tid];
        int   t0 = wc[tid];
        #pragma unroll
        for (int st = 4; st > 0; st >>= 1)
            t1 += __shfl_xor_sync(0x000000ffu, t1, st);
        t0 = __reduce_add_sync(0x000000ffu, t0);

        if (tid == 0) {
            atomicAdd(&g_acc[b][0], (unsigned long long)t0);
            atomicAdd(&g_acc[b][1], (unsigned long long)llrint((double)t1 * FIXSCALE));
            __threadfence();

            const unsigned int ticket = atomicAdd(&g_done, 1u);
            if (ticket == NBLOCKS - 1) {
                float total = 0.0f, ns = 0.0f;
                #pragma unroll
                for (int bb = 0; bb < BATCH; bb++) {
                    const double cnt_b = (double)g_acc[bb][0];
                    if (cnt_b > 0.0) {
                        const double s = (double)g_acc[bb][1] / FIXSCALE;
                        total += (float)(0.5 * s / fmax(cnt_b, 1.0));
                        ns += 1.0f;
                    }
                }
                out[0] = (ns > 0.0f) ? (total / fmaxf(ns, 1.0f)) : total;
                #pragma unroll
                for (int bb = 0; bb < BATCH; bb++) {
                    g_acc[bb][0] = 0ull; g_acc[bb][1] = 0ull;
                }
                __threadfence();
                g_done = 0u;
            }
        }
    }
}

extern "C" void kernel_launch(void* const* d_in, const int* in_sizes, int n_in,
                              void* d_out, int out_size)
{
    const float* arrs[3] = { (const float*)d_in[0],
                             (const float*)d_in[1],
                             (const float*)d_in[2] };
    const float* logits = arrs[0];
    const float* boxes  = arrs[1];
    const float* hmap   = arrs[2];
    if (n_in >= 3) {
        int bi = -1;
        for (int i = 0; i < 3; i++)
            if (in_sizes[i] == BATCH * NBOX * 7) { bi = i; break; }
        if (bi >= 0) {
            boxes = arrs[bi];
            int o0 = -1, o1 = -1;
            for (int i = 0; i < 3; i++) {
                if (i == bi) continue;
                if (o0 < 0) o0 = i; else o1 = i;
            }
            logits = arrs[o0];
            hmap   = arrs[o1];
        }
    }

    dim3 block(256, 1, 1);
    dim3 grid(TXN, TYN, BATCH);
    hm_loss_fused_kernel<<<grid, block>>>(logits, boxes, hmap, (float*)d_out);
}

// round 10
// speedup vs baseline: 1.0175x; 1.0175x over previous
#include <cuda_runtime.h>
#include <math.h>

#define XS 540
#define YS 540
#define BATCH 4
#define NBOX 64
#define TILE_X 64
#define TILE_Y 32
#define TXN 9           // ceil(540/64)
#define TYN 17          // ceil(540/32)
#define NBLOCKS (TXN*TYN*BATCH)
#define FIXSCALE 67108864.0   // 2^26

__device__ unsigned long long g_acc[BATCH][2];
__device__ unsigned int g_done;

struct BoxC { float cx, cy, c, s, hw, hl, hv; };

__global__ void __launch_bounds__(256)
hm_loss_fused_kernel(const float* __restrict__ logits,
                     const float* __restrict__ boxes,
                     const float* __restrict__ hm,
                     float* __restrict__ out)
{
    __shared__ BoxC bc[NBOX];
    __shared__ unsigned int sm_mask[2];
    __shared__ float ws[8];
    __shared__ int   wc[8];

    const int b    = blockIdx.z;
    const int tid  = threadIdx.x;
    const int lane = tid & 31;
    const int wrp  = tid >> 5;

    // ---- box loads FIRST (they feed the barrier everyone waits on) ----
    float p0, p1, p3, p4, p5, p6;
    if (tid < NBOX) {
        const float* p = boxes + (b * NBOX + tid) * 7;
        p0 = p[0]; p1 = p[1]; p3 = p[3]; p4 = p[4]; p5 = p[5]; p6 = p[6];
    }

    // ---- pixel prefetch: thread = 2 rows x 4 contiguous x px ----
    const int x4 = blockIdx.x * TILE_X + (tid & 15) * 4;
    const int y0 = blockIdx.y * TILE_Y + (tid >> 4);      // rows y0, y0+16
    const int y1 = y0 + 16;
    const bool xok = (x4 + 3 < XS);
    const bool oka = xok && (y0 < YS);
    const bool okb = xok && (y1 < YS);

    float4 xa = make_float4(0.f,0.f,0.f,0.f), ha = xa;
    float4 xb = xa, hb = xa;
    if (oka) {
        const int idx = (b * YS + y0) * XS + x4;
        xa = *reinterpret_cast<const float4*>(logits + idx);
        ha = *reinterpret_cast<const float4*>(hm + idx);
    }
    if (okb) {
        const int idx = (b * YS + y1) * XS + x4;
        xb = *reinterpret_cast<const float4*>(logits + idx);
        hb = *reinterpret_cast<const float4*>(hm + idx);
    }

    // ---- box transform + cull + ballot ----
    if (tid < NBOX) {
        BoxC v;
        v.cx = (p0 + 54.0f) * 5.0f;
        v.cy = (p1 + 54.0f) * 5.0f;
        v.hw = p3 * 2.5f;
        v.hl = p4 * 2.5f;
        float sn, cn;
        __sincosf(p6, &sn, &cn);
        v.c  = cn;           // cos(-theta)
        v.s  = -sn;          // sin(-theta)
        v.hv = p5 * 0.2f;
        bc[tid] = v;

        const float ex = fabsf(v.c) * v.hw + fabsf(v.s) * v.hl;
        const float ey = fabsf(v.s) * v.hw + fabsf(v.c) * v.hl;
        const float tx0 = (float)(blockIdx.x * TILE_X);
        const float ty0 = (float)(blockIdx.y * TILE_Y);
        const bool hit = (v.cx - ex <= tx0 + (float)(TILE_X - 1)) && (v.cx + ex >= tx0) &&
                         (v.cy - ey <= ty0 + (float)(TILE_Y - 1)) && (v.cy + ey >= ty0);
        const unsigned int m = __ballot_sync(0xffffffffu, hit);
        if (lane == 0) sm_mask[wrp] = m;
    }
    __syncthreads();

    const unsigned int m0 = sm_mask[0];
    const unsigned int m1 = sm_mask[1];

    // ---- raster: forward order, overwrite => last box wins ----
    float gta[4] = {0.f,0.f,0.f,0.f};
    float gtb[4] = {0.f,0.f,0.f,0.f};
    {
        const float fx0 = (float)x4;
        const float fy  = (float)y0;
        #pragma unroll
        for (int half = 0; half < 2; half++) {
            unsigned int mm = half ? m1 : m0;
            const int base = half ? 32 : 0;
            while (mm) {
                const int i = __ffs(mm) - 1;
                mm &= mm - 1u;
                const BoxC v = bc[base + i];
                const float dx = fx0 - v.cx;
                const float dy = fy - v.cy;
                float lxa = dx * v.c - dy * v.s;
                float lya = dx * v.s + dy * v.c;
                float lxb = fmaf(-16.0f, v.s, lxa);   // row y0+16
                float lyb = fmaf( 16.0f, v.c, lya);
                #pragma unroll
                for (int j = 0; j < 4; j++) {
                    const bool ia = (fabsf(lxa) <= v.hw) && (fabsf(lya) <= v.hl);
                    const bool ib = (fabsf(lxb) <= v.hw) && (fabsf(lyb) <= v.hl);
                    gta[j] = ia ? v.hv : gta[j];
                    gtb[j] = ib ? v.hv : gtb[j];
                    lxa += v.c; lya += v.s;
                    lxb += v.c; lyb += v.s;
                }
            }
        }
    }

    // ---- loss: branch-free, 8 px, two accumulators ----
    float sc0 = 0.0f, sc1 = 0.0f;
    int   cv = 0;
    const float* xva = &xa.x; const float* hha = &ha.x;
    const float* xvb = &xb.x; const float* hhb = &hb.x;
    #pragma unroll
    for (int j = 0; j < 8; j++) {
        const bool  row2  = (j >= 4);
        const float g     = row2 ? gtb[j - 4] : gta[j];
        const float xl    = row2 ? xvb[j - 4] : xva[j];
        const float hhv   = row2 ? hhb[j - 4] : hha[j];
        const bool  okr   = row2 ? okb : oka;

        const bool pos = (g > 0.0f);
        const bool valid = okr && (pos || (hhv > 0.0f));

        const float weight = pos ? 5.0f : 0.1f;
        const float e  = __expf(-fabsf(xl));
        const float d  = 1.0f + e;
        const float bce = fmaxf(xl, 0.0f) - xl * g + __logf(d);
        const float rd = __fdividef(1.0f, d);
        const float p  = (xl >= 0.0f) ? rd : e * rd;    // sigmoid
        const float u  = fmaf(p, 1.0f - 2.0f * g, g);   // 1 - p_t
        const float aw = 0.75f - 0.5f * g;
        const float contrib = weight * bce * fmaf(u * u, aw, 1.0f);
        if (j & 1) sc1 += valid ? contrib : 0.0f;
        else       sc0 += valid ? contrib : 0.0f;
        cv += valid ? 1 : 0;
    }
    float sc = sc0 + sc1;

    const int cnt = __reduce_add_sync(0xffffffffu, cv);
    #pragma unroll
    for (int st = 16; st > 0; st >>= 1)
        sc += __shfl_xor_sync(0xffffffffu, sc, st);
    if (lane == 0) { ws[wrp] = sc; wc[wrp] = cnt; }
    __syncthreads();

    // ---- final combine in warp 0 (8 lanes) ----
    if (tid < 8) {
        float t1 = ws[tid];
        int   t0 = wc[tid];
        #pragma unroll
        for (int st = 4; st > 0; st >>= 1)
            t1 += __shfl_xor_sync(0x000000ffu, t1, st);
        t0 = __reduce_add_sync(0x000000ffu, t0);

        if (tid == 0) {
            atomicAdd(&g_acc[b][0], (unsigned long long)t0);
            atomicAdd(&g_acc[b][1], (unsigned long long)llrint((double)t1 * FIXSCALE));
            __threadfence();

            const unsigned int ticket = atomicAdd(&g_done, 1u);
            if (ticket == NBLOCKS - 1) {
                float total = 0.0f, ns = 0.0f;
                #pragma unroll
                for (int bb = 0; bb < BATCH; bb++) {
                    const double cnt_b = (double)g_acc[bb][0];
                    if (cnt_b > 0.0) {
                        const double s = (double)g_acc[bb][1] / FIXSCALE;
                        total += (float)(0.5 * s / fmax(cnt_b, 1.0));
                        ns += 1.0f;
                    }
                }
                out[0] = (ns > 0.0f) ? (total / fmaxf(ns, 1.0f)) : total;
                #pragma unroll
                for (int bb = 0; bb < BATCH; bb++) {
                    g_acc[bb][0] = 0ull; g_acc[bb][1] = 0ull;
                }
                __threadfence();
                g_done = 0u;
            }
        }
    }
}

extern "C" void kernel_launch(void* const* d_in, const int* in_sizes, int n_in,
                              void* d_out, int out_size)
{
    const float* arrs[3] = { (const float*)d_in[0],
                             (const float*)d_in[1],
                             (const float*)d_in[2] };
    const float* logits = arrs[0];
    const float* boxes  = arrs[1];
    const float* hmap   = arrs[2];
    if (n_in >= 3) {
        int bi = -1;
        for (int i = 0; i < 3; i++)
            if (in_sizes[i] == BATCH * NBOX * 7) { bi = i; break; }
        if (bi >= 0) {
            boxes = arrs[bi];
            int o0 = -1, o1 = -1;
            for (int i = 0; i < 3; i++) {
                if (i == bi) continue;
                if (o0 < 0) o0 = i; else o1 = i;
            }
            logits = arrs[o0];
            hmap   = arrs[o1];
        }
    }

    dim3 block(256, 1, 1);
    dim3 grid(TXN, TYN, BATCH);
    hm_loss_fused_kernel<<<grid, block>>>(logits, boxes, hmap, (float*)d_out);
}

// round 11
// speedup vs baseline: 1.0201x; 1.0025x over previous
#include <cuda_runtime.h>
#include <math.h>

#define XS 540
#define YS 540
#define BATCH 4
#define NBOX 64
#define TILE 32
#define TXN 17
#define TYN 17
#define NBLOCKS (TXN*TYN*BATCH)
#define FIXSCALE 67108864.0   // 2^26

__device__ unsigned long long g_acc[BATCH][2];
__device__ unsigned int g_done;

__global__ void __launch_bounds__(256)
hm_loss_fused_kernel(const float* __restrict__ logits,
                     const float* __restrict__ boxes,
                     const float* __restrict__ hm,
                     float* __restrict__ out)
{
    // bc4[i][0] = {cx, cy, c, s};  bc4[i][1] = {hw, hl, hv, 0}
    __shared__ float4 bc4[NBOX][2];
    __shared__ unsigned char mask_bytes[8];
    __shared__ float ws[8];
    __shared__ int   wc[8];

    const int b    = blockIdx.z;
    const int tid  = threadIdx.x;
    const int lane = tid & 31;
    const int wrp  = tid >> 5;

    // ---- pixel prefetch: thread = 4 contiguous x px in one row ----
    const int x4 = blockIdx.x * TILE + (lane & 7) * 4;
    const int y  = blockIdx.y * TILE + (tid >> 3);
    const bool ok = (x4 + 3 < XS) && (y < YS);

    float4 xl4 = make_float4(0.f, 0.f, 0.f, 0.f);
    float4 hh4 = make_float4(0.f, 0.f, 0.f, 0.f);
    if (ok) {
        const int idx = (b * YS + y) * XS + x4;
        xl4 = *reinterpret_cast<const float4*>(logits + idx);
        hh4 = *reinterpret_cast<const float4*>(hm + idx);
    }

    // ---- balanced box prologue: warp w handles boxes [8w, 8w+8), lanes 0-7 ----
    bool hit = false;
    if (lane < 8) {
        const int bi = wrp * 8 + lane;
        const float* p = boxes + (b * NBOX + bi) * 7;
        const float p0 = p[0], p1 = p[1], p3 = p[3], p4 = p[4], p5 = p[5], p6 = p[6];

        const float cx = (p0 + 54.0f) * 5.0f;
        const float cy = (p1 + 54.0f) * 5.0f;
        const float hw = p3 * 2.5f;
        const float hl = p4 * 2.5f;
        float sn, cn;
        __sincosf(p6, &sn, &cn);
        const float c = cn;           // cos(-theta)
        const float s = -sn;          // sin(-theta)
        const float hv = p5 * 0.2f;

        bc4[bi][0] = make_float4(cx, cy, c, s);
        bc4[bi][1] = make_float4(hw, hl, hv, 0.0f);

        const float ex = fabsf(c) * hw + fabsf(s) * hl;
        const float ey = fabsf(s) * hw + fabsf(c) * hl;
        const float tx0 = (float)(blockIdx.x * TILE);
        const float ty0 = (float)(blockIdx.y * TILE);
        hit = (cx - ex <= tx0 + (float)(TILE - 1)) && (cx + ex >= tx0) &&
              (cy - ey <= ty0 + (float)(TILE - 1)) && (cy + ey >= ty0);
    }
    const unsigned int wm = __ballot_sync(0xffffffffu, hit) & 0xffu;
    if (lane == 0) mask_bytes[wrp] = (unsigned char)wm;
    __syncthreads();

    const unsigned long long mask =
        *reinterpret_cast<const unsigned long long*>(mask_bytes);
    const unsigned int m0 = (unsigned int)mask;
    const unsigned int m1 = (unsigned int)(mask >> 32);

    // ---- raster: forward order, overwrite => last box wins ----
    float gt[4] = {0.f, 0.f, 0.f, 0.f};
    {
        const float fx0 = (float)x4;
        const float fy  = (float)y;
        #pragma unroll
        for (int half = 0; half < 2; half++) {
            unsigned int mm = half ? m1 : m0;
            const int base = half ? 32 : 0;
            while (mm) {
                const int i = __ffs(mm) - 1;
                mm &= mm - 1u;
                const float4 a = bc4[base + i][0];   // cx, cy, c, s
                const float4 e = bc4[base + i][1];   // hw, hl, hv
                const float dx = fx0 - a.x;
                const float dy = fy - a.y;
                float lx = dx * a.z - dy * a.w;
                float ly = dx * a.w + dy * a.z;
                #pragma unroll
                for (int j = 0; j < 4; j++) {
                    const bool inside = (fabsf(lx) <= e.x) && (fabsf(ly) <= e.y);
                    gt[j] = inside ? e.z : gt[j];
                    lx += a.z;
                    ly += a.w;
                }
            }
        }
    }

    // ---- loss: branch-free, two accumulators ----
    float sc0 = 0.0f, sc1 = 0.0f;
    int   cv = 0;
    const float* xvp = &xl4.x;
    const float* hhp = &hh4.x;
    #pragma unroll
    for (int j = 0; j < 4; j++) {
        const float g  = gt[j];
        const bool pos = (g > 0.0f);
        const bool valid = ok && (pos || (hhp[j] > 0.0f));
        const float xl = xvp[j];

        const float weight = pos ? 5.0f : 0.1f;
        const float e  = __expf(-fabsf(xl));
        const float d  = 1.0f + e;
        const float bce = fmaxf(xl, 0.0f) - xl * g + __logf(d);
        const float rd = __fdividef(1.0f, d);
        const float p  = (xl >= 0.0f) ? rd : e * rd;    // sigmoid
        const float u  = fmaf(p, 1.0f - 2.0f * g, g);   // 1 - p_t
        const float aw = 0.75f - 0.5f * g;
        const float contrib = weight * bce * fmaf(u * u, aw, 1.0f);
        if (j & 1) sc1 += valid ? contrib : 0.0f;
        else       sc0 += valid ? contrib : 0.0f;
        cv += valid ? 1 : 0;
    }
    float sc = sc0 + sc1;

    const int cnt = __reduce_add_sync(0xffffffffu, cv);
    #pragma unroll
    for (int st = 16; st > 0; st >>= 1)
        sc += __shfl_xor_sync(0xffffffffu, sc, st);
    if (lane == 0) { ws[wrp] = sc; wc[wrp] = cnt; }
    __syncthreads();

    // ---- final combine in warp 0 (8 lanes) ----
    if (tid < 8) {
        float t1 = ws[tid];
        int   t0 = wc[tid];
        #pragma unroll
        for (int st = 4; st > 0; st >>= 1)
            t1 += __shfl_xor_sync(0x000000ffu, t1, st);
        t0 = __reduce_add_sync(0x000000ffu, t0);

        if (tid == 0) {
            atomicAdd(&g_acc[b][0], (unsigned long long)t0);
            atomicAdd(&g_acc[b][1], (unsigned long long)llrint((double)t1 * FIXSCALE));
            __threadfence();

            const unsigned int ticket = atomicAdd(&g_done, 1u);
            if (ticket == NBLOCKS - 1) {
                float total = 0.0f, ns = 0.0f;
                #pragma unroll
                for (int bb = 0; bb < BATCH; bb++) {
                    const double cnt_b = (double)g_acc[bb][0];
                    if (cnt_b > 0.0) {
                        const double s = (double)g_acc[bb][1] / FIXSCALE;
                        total += (float)(0.5 * s / fmax(cnt_b, 1.0));
                        ns += 1.0f;
                    }
                }
                out[0] = (ns > 0.0f) ? (total / fmaxf(ns, 1.0f)) : total;
                #pragma unroll
                for (int bb = 0; bb < BATCH; bb++) {
                    g_acc[bb][0] = 0ull; g_acc[bb][1] = 0ull;
                }
                __threadfence();
                g_done = 0u;
            }
        }
    }
}

extern "C" void kernel_launch(void* const* d_in, const int* in_sizes, int n_in,
                              void* d_out, int out_size)
{
    const float* arrs[3] = { (const float*)d_in[0],
                             (const float*)d_in[1],
                             (const float*)d_in[2] };
    const float* logits = arrs[0];
    const float* boxes  = arrs[1];
    const float* hmap   = arrs[2];
    if (n_in >= 3) {
        int bi = -1;
        for (int i = 0; i < 3; i++)
            if (in_sizes[i] == BATCH * NBOX * 7) { bi = i; break; }
        if (bi >= 0) {
            boxes = arrs[bi];
            int o0 = -1, o1 = -1;
            for (int i = 0; i < 3; i++) {
                if (i == bi) continue;
                if (o0 < 0) o0 = i; else o1 = i;
            }
            logits = arrs[o0];
            hmap   = arrs[o1];
        }
    }

    dim3 block(256, 1, 1);
    dim3 grid(TXN, TYN, BATCH);
    hm_loss_fused_kernel<<<grid, block>>>(logits, boxes, hmap, (float*)d_out);
}